// round 13
// baseline (speedup 1.0000x reference)
#include <cuda_runtime.h>
#include <cuda_bf16.h>
#include <cstdint>

// ---------------- problem constants ----------------
#define BSZ   256
#define DIM   128
#define QK    131072
#define NC    131073
#define OUT_ELEMS (BSZ * (long long)NC)      // 33,554,688
#define PROBS_OFF OUT_ELEMS
#define MEM_OFF   (OUT_ELEMS + 1)
#define T_INV 14.2857142857142857f
#define OUTPUT_SIZE 1000000.0f
#define GRID_GEMM 148
#define NTILES    2048                        // 1024 bn x 2 bm
#define GTHREADS  512

// split kernel block layout
#define MEMBLKS  8192      // mem: 4,194,304 float4 / 2 per thread / 256
#define QBLKS    16        // q: 8,192 float4 / 2 per thread / 256
#define SPLIT_GRID (MEMBLKS + QBLKS + 1)

// ---------------- device scratch ----------------
__device__ float g_rowsum[BSZ];
__device__ float g_invZ;
__device__ int   g_done  = 0;   // monotonic ticket counter (never reset)
__device__ int   g_epoch = 0;   // monotonic epoch (never reset)
__device__ __nv_bfloat16 g_mem_hi[QK * DIM];   // 32 MB
__device__ __nv_bfloat16 g_mem_lo[QK * DIM];   // 32 MB
__device__ __nv_bfloat16 g_q_hi[BSZ * DIM];
__device__ __nv_bfloat16 g_q_lo[BSZ * DIM];

// ---------------- helpers ----------------
__device__ __forceinline__ uint32_t smem_u32(const void* p) {
    uint32_t a;
    asm("{ .reg .u64 t; cvta.to.shared.u64 t, %1; cvt.u32.u64 %0, t; }" : "=r"(a) : "l"(p));
    return a;
}
__device__ __forceinline__ void ldm_x4(uint32_t* r, uint32_t addr) {
    asm volatile("ldmatrix.sync.aligned.m8n8.x4.shared.b16 {%0,%1,%2,%3}, [%4];"
                 : "=r"(r[0]), "=r"(r[1]), "=r"(r[2]), "=r"(r[3]) : "r"(addr));
}
__device__ __forceinline__ void mma_bf16(float* d, const uint32_t* a, uint32_t b0, uint32_t b1) {
    asm volatile(
        "mma.sync.aligned.m16n8k16.row.col.f32.bf16.bf16.f32 "
        "{%0,%1,%2,%3}, {%4,%5,%6,%7}, {%8,%9}, {%0,%1,%2,%3};"
        : "+f"(d[0]), "+f"(d[1]), "+f"(d[2]), "+f"(d[3])
        : "r"(a[0]), "r"(a[1]), "r"(a[2]), "r"(a[3]), "r"(b0), "r"(b1));
}
#define CP_ASYNC16(dst, src) \
    asm volatile("{ .reg .u64 g; cvta.to.global.u64 g, %1; cp.async.cg.shared.global [%0], [g], 16; }" \
                 :: "r"(dst), "l"(src) : "memory")
#define CP_COMMIT() asm volatile("cp.async.commit_group;" ::: "memory")
#define CP_WAIT1()  asm volatile("cp.async.wait_group 1;" ::: "memory")
#define CP_WAIT0()  asm volatile("cp.async.wait_group 0;" ::: "memory")

// ---- packed f32x2 ----
__device__ __forceinline__ unsigned long long dup2(float x) {
    unsigned long long r; unsigned int u = __float_as_uint(x);
    asm("mov.b64 %0, {%1, %1};" : "=l"(r) : "r"(u));
    return r;
}
__device__ __forceinline__ unsigned long long fma2(unsigned long long a,
                                                   unsigned long long b,
                                                   unsigned long long c) {
    unsigned long long d;
    asm("fma.rn.f32x2 %0, %1, %2, %3;" : "=l"(d) : "l"(a), "l"(b), "l"(c));
    return d;
}
__device__ __forceinline__ unsigned long long add2(unsigned long long a, unsigned long long b) {
    unsigned long long d;
    asm("add.rn.f32x2 %0, %1, %2;" : "=l"(d) : "l"(a), "l"(b));
    return d;
}
__device__ __forceinline__ unsigned long long mul2(unsigned long long a, unsigned long long b) {
    unsigned long long d;
    asm("mul.rn.f32x2 %0, %1, %2;" : "=l"(d) : "l"(a), "l"(b));
    return d;
}

// exp(s/T) for a pair, via packed exp2 on the FMA pipe.
__device__ __forceinline__ float2 exp_pair(float a, float b) {
    unsigned long long sp;
    asm("mov.b64 %0, {%1,%2};" : "=l"(sp) : "f"(a), "f"(b));
    const unsigned long long S  = dup2(20.60992908f);       // (1/0.07)*log2(e)
    const unsigned long long MG = dup2(12582912.0f);        // 1.5*2^23
    unsigned long long t  = fma2(sp, S, MG);
    unsigned long long nf = add2(t, dup2(-12582912.0f));    // n as float
    unsigned long long f  = fma2(sp, S, nf ^ 0x8000000080000000ULL);  // y - n
    unsigned long long r  = fma2(f, dup2(0.00133335581464f), dup2(0.00961812910763f));
    r = fma2(r, f, dup2(0.0555041086648f));
    r = fma2(r, f, dup2(0.240226506959f));
    r = fma2(r, f, dup2(0.69314718056f));
    r = fma2(r, f, dup2(1.0f));
    uint32_t t0, t1;
    asm("mov.b64 {%0,%1}, %2;" : "=r"(t0), "=r"(t1) : "l"(t));
    uint32_t sb0 = (t0 << 23) + 0x3F800000u;
    uint32_t sb1 = (t1 << 23) + 0x3F800000u;
    unsigned long long sc;
    asm("mov.b64 %0, {%1,%2};" : "=l"(sc) : "r"(sb0), "r"(sb1));
    unsigned long long res = mul2(r, sc);
    float x, y;
    asm("mov.b64 {%0,%1}, %2;" : "=f"(x), "=f"(y) : "l"(res));
    return make_float2(x, y);
}

// ---- bit-trick split: two floats -> packed hi bf16x2 + packed lo bf16x2 ----
__device__ __forceinline__ void split2(float x, float y, uint32_t& hi, uint32_t& lo) {
    uint32_t h;
    asm("cvt.rn.bf16x2.f32 %0, %1, %2;" : "=r"(h) : "f"(y), "f"(x));  // upper=y, lower=x
    float hx = __uint_as_float(h << 16);
    float hy = __uint_as_float(h & 0xFFFF0000u);
    float rx = x - hx, ry = y - hy;
    uint32_t l;
    asm("cvt.rn.bf16x2.f32 %0, %1, %2;" : "=r"(l) : "f"(ry), "f"(rx));
    hi = h; lo = l;
}
// 8 consecutive floats (2 float4) -> hi uint4 + lo uint4
__device__ __forceinline__ void split8(float4 v0, float4 v1, uint4& hi, uint4& lo) {
    split2(v0.x, v0.y, hi.x, lo.x);
    split2(v0.z, v0.w, hi.y, lo.y);
    split2(v1.x, v1.y, hi.z, lo.z);
    split2(v1.z, v1.w, hi.w, lo.w);
}

// ---------------- K0: loop-free split + zero + l_pos ----------------
__global__ void splitmain_k(const float* __restrict__ q, const float* __restrict__ k,
                            const float* __restrict__ mem, float* __restrict__ out) {
    int b = blockIdx.x;
    int t = threadIdx.x;
    if (b < MEMBLKS) {
        // mem split: thread handles 2 consecutive float4 (8 floats)
        int tid = b * 256 + t;                 // < 2,097,152
        const float4* src = reinterpret_cast<const float4*>(mem) + tid * 2;
        float4 v0 = src[0];
        float4 v1 = src[1];
        uint4 hi, lo;
        split8(v0, v1, hi, lo);
        reinterpret_cast<uint4*>(g_mem_hi)[tid] = hi;
        reinterpret_cast<uint4*>(g_mem_lo)[tid] = lo;
    } else if (b < MEMBLKS + QBLKS) {
        // q split
        int tid = (b - MEMBLKS) * 256 + t;     // < 4096
        const float4* src = reinterpret_cast<const float4*>(q) + tid * 2;
        float4 v0 = src[0];
        float4 v1 = src[1];
        uint4 hi, lo;
        split8(v0, v1, hi, lo);
        reinterpret_cast<uint4*>(g_q_hi)[tid] = hi;
        reinterpret_cast<uint4*>(g_q_lo)[tid] = lo;
    } else {
        // zero rowsums + l_pos column
        g_rowsum[t] = 0.f;
        __syncthreads();
        int vid = t & 63;
        const float* qb = q + t * DIM;
        float s = 0.f;
        #pragma unroll
        for (int c = 0; c < 4; c++) {
            int r = vid + c * 64;
            if (r == t) continue;
            const float* kr = k + r * DIM;
            float d = 0.f;
            #pragma unroll
            for (int j = 0; j < DIM; j++) d += kr[j] * qb[j];
            s += d;
        }
        s *= (1.0f / 3.0f);
        float e = __expf(s * T_INV);
        out[(long long)t * NC] = e;
        atomicAdd(&g_rowsum[t], e);
    }
}

// ---------------- K1: persistent GEMM + memup + finalize + scale --------
// SMEM 192KB: A hi/lo (64KB resident, 128 rows) + two B buffers (64KB each).
extern __shared__ char smem_g[];

__device__ __forceinline__ void issueB(int bn, int buf, uint32_t sbase, int t) {
    const uint4* hi = reinterpret_cast<const uint4*>(g_mem_hi) + (size_t)bn * 2048;
    const uint4* lo = reinterpret_cast<const uint4*>(g_mem_lo) + (size_t)bn * 2048;
    uint32_t base = sbase + 65536 + (uint32_t)buf * 65536;
    #pragma unroll
    for (int it = 0; it < 8; it++) {
        int fid = it * GTHREADS + t;
        int arr = fid >> 11;
        int within = fid & 2047;
        int row = within >> 4, ch = within & 15;
        const uint4* src = (arr ? lo : hi) + row * 16 + ch;
        uint32_t dst = base + (uint32_t)(arr * 32768 + row * 256 + ((ch ^ (row & 7)) << 4));
        CP_ASYNC16(dst, src);
    }
}
__device__ __forceinline__ void stageA(int bm, int t) {
    const uint4* hi = reinterpret_cast<const uint4*>(g_q_hi) + (size_t)bm * 2048;
    const uint4* lo = reinterpret_cast<const uint4*>(g_q_lo) + (size_t)bm * 2048;
    #pragma unroll
    for (int it = 0; it < 8; it++) {
        int fid = it * GTHREADS + t;
        int arr = fid >> 11;
        int within = fid & 2047;
        int row = within >> 4, ch = within & 15;
        uint4 v = (arr ? lo : hi)[row * 16 + ch];
        *reinterpret_cast<uint4*>(smem_g + arr * 32768 + row * 256 + ((ch ^ (row & 7)) << 4)) = v;
    }
}

__global__ __launch_bounds__(GTHREADS, 1)
void gemm_k(float* __restrict__ out, const float* __restrict__ kk,
            const float* __restrict__ memp) {
    __shared__ int isLast;
    uint32_t sbase = smem_u32(smem_g);
    int t = threadIdx.x;
    int e0 = *((volatile int*)&g_epoch);   // epoch snapshot before any arrival
    int w = t >> 5, lane = t & 31;
    int wm = w >> 2, wn = w & 3;          // 4x4 warps; warp tile 32 rows x 32 cols
    int a_r = (lane & 7) + ((lane >> 3) & 1) * 8;
    int a_c = (lane >> 4) & 1;
    int b_r = (lane & 7) + ((lane >> 4) & 1) * 8;
    int b_c = (lane >> 3) & 1;
    int grp = lane >> 2, tid4 = lane & 3;

    float rs[2][2] = {{0.f, 0.f}, {0.f, 0.f}};

    int tile0 = blockIdx.x;
    int curBm = tile0 >> 10;

    issueB(tile0 & 1023, 0, sbase, t);
    CP_COMMIT();
    stageA(curBm, t);

    const uint32_t AH = sbase, AL = sbase + 32768;

    int idx = 0;
    for (int tile = tile0; tile < NTILES; tile += GRID_GEMM, idx++) {
        int nxt = tile + GRID_GEMM;
        if (nxt < NTILES) {
            issueB(nxt & 1023, (idx + 1) & 1, sbase, t);
            CP_COMMIT();
            CP_WAIT1();
        } else {
            CP_WAIT0();
        }
        __syncthreads();

        int bm = tile >> 10;
        if (bm != curBm) {
            #pragma unroll
            for (int mt = 0; mt < 2; mt++) {
                int r0 = curBm * 128 + wm * 32 + mt * 16 + grp;
                atomicAdd(&g_rowsum[r0], rs[mt][0]);
                atomicAdd(&g_rowsum[r0 + 8], rs[mt][1]);
                rs[mt][0] = rs[mt][1] = 0.f;
            }
            curBm = bm;
            stageA(bm, t);
            __syncthreads();
        }

        uint32_t BH = sbase + 65536 + (uint32_t)(idx & 1) * 65536;
        uint32_t BL = BH + 32768;
        int bn = tile & 1023;

        float acc[2][4][4];
        #pragma unroll
        for (int mt = 0; mt < 2; mt++)
            #pragma unroll
            for (int nt = 0; nt < 4; nt++)
                #pragma unroll
                for (int r = 0; r < 4; r++) acc[mt][nt][r] = 0.f;

        #pragma unroll
        for (int ks = 0; ks < 8; ks++) {
            uint32_t ah[2][4], al[2][4];
            #pragma unroll
            for (int mt = 0; mt < 2; mt++) {
                int r = wm * 32 + mt * 16 + a_r;
                int ch = ks * 2 + a_c;
                uint32_t off = (uint32_t)(r * 256 + ((ch ^ (r & 7)) << 4));
                ldm_x4(ah[mt], AH + off);
                ldm_x4(al[mt], AL + off);
            }
            #pragma unroll
            for (int np = 0; np < 2; np++) {
                int n = wn * 32 + np * 16 + b_r;
                int ch = ks * 2 + b_c;
                uint32_t off = (uint32_t)(n * 256 + ((ch ^ (n & 7)) << 4));
                uint32_t bh[4], bl[4];
                ldm_x4(bh, BH + off);
                ldm_x4(bl, BL + off);
                #pragma unroll
                for (int sub = 0; sub < 2; sub++) {
                    int nt = np * 2 + sub;
                    #pragma unroll
                    for (int mt = 0; mt < 2; mt++) {
                        mma_bf16(acc[mt][nt], ah[mt], bh[2 * sub], bh[2 * sub + 1]);
                        mma_bf16(acc[mt][nt], ah[mt], bl[2 * sub], bl[2 * sub + 1]);
                        mma_bf16(acc[mt][nt], al[mt], bh[2 * sub], bh[2 * sub + 1]);
                    }
                }
            }
        }

        // ---- epilogue: poly exp (FMA pipe), store, rowsum ----
        #pragma unroll
        for (int mt = 0; mt < 2; mt++) {
            int r0l = wm * 32 + mt * 16 + grp;
            long long m0 = (long long)(bm * 128 + r0l);
            long long base0 = m0 * NC + 1 + (long long)bn * 128 + wn * 32;
            long long base1 = base0 + 8LL * NC;
            float s0 = 0.f, s1 = 0.f;
            #pragma unroll
            for (int nt = 0; nt < 4; nt++) {
                int cb = nt * 8 + tid4 * 2;
                float2 p0 = exp_pair(acc[mt][nt][0], acc[mt][nt][1]);
                float2 p1 = exp_pair(acc[mt][nt][2], acc[mt][nt][3]);
                out[base0 + cb]     = p0.x;
                out[base0 + cb + 1] = p0.y;
                out[base1 + cb]     = p1.x;
                out[base1 + cb + 1] = p1.y;
                s0 += p0.x + p0.y;
                s1 += p1.x + p1.y;
            }
            rs[mt][0] += s0; rs[mt][1] += s1;
        }
        __syncthreads();
    }

    #pragma unroll
    for (int mt = 0; mt < 2; mt++) {
        int r0 = curBm * 128 + wm * 32 + mt * 16 + grp;
        atomicAdd(&g_rowsum[r0], rs[mt][0]);
        atomicAdd(&g_rowsum[r0 + 8], rs[mt][1]);
    }

    // ---- memup tail (independent of Z) ----
    {
        const long long N = (long long)QK * DIM;
        long long stride = (long long)GRID_GEMM * GTHREADS;
        for (long long p = (long long)blockIdx.x * GTHREADS + t; p < N; p += stride) {
            int r = (int)(p >> 7), d = (int)(p & 127);
            float v;
            if (r < 64) {
                v = 0.25f * (kk[r * DIM + d] + kk[(r + 64) * DIM + d] +
                             kk[(r + 128) * DIM + d] + kk[(r + 192) * DIM + d]);
            } else {
                v = memp[p];
            }
            out[MEM_OFF + p] = v;
        }
    }

    // ---- grid-wide barrier: last CTA finalizes Z/invZ/probs, bumps epoch ----
    __threadfence();
    __syncthreads();
    if (t == 0) isLast = ((atomicAdd(&g_done, 1) % GRID_GEMM) == GRID_GEMM - 1);
    __syncthreads();
    if (isLast) {
        float* s = reinterpret_cast<float*>(smem_g);   // reuse dyn smem
        if (t < 256) {
            volatile float* vr = g_rowsum;
            float rsv = vr[t];
            float e0v = out[(long long)t * NC];
            s[t] = rsv;
            s[256 + t] = e0v / rsv;
        }
        __syncthreads();
        for (int st = 128; st > 0; st >>= 1) {
            if (t < st) { s[t] += s[t + st]; s[256 + t] += s[256 + t + st]; }
            __syncthreads();
        }
        if (t == 0) {
            float Z = s[0] / ((float)BSZ * (float)NC) * OUTPUT_SIZE;
            g_invZ = 1.f / Z;
            out[PROBS_OFF] = s[256] * (1.0f / 256.0f);
            __threadfence();
            atomicAdd(&g_epoch, 1);
        }
    }
    // spin until epoch flips (all CTAs resident -> no deadlock)
    if (t == 0) {
        while (*((volatile int*)&g_epoch) == e0) __nanosleep(64);
    }
    __syncthreads();
    __threadfence();   // gpu-scope: flush/invalidate L1 before reading peers' out

    // ---- scale own disjoint chunk of out by 1/Z ----
    {
        float inv = g_invZ;
        const long long n4 = OUT_ELEMS / 4;
        long long c0 = (long long)blockIdx.x * n4 / GRID_GEMM;
        long long c1 = (long long)(blockIdx.x + 1) * n4 / GRID_GEMM;
        float4* o4 = reinterpret_cast<float4*>(out);
        for (long long p = c0 + t; p < c1; p += GTHREADS) {
            float4 v = o4[p];
            v.x *= inv; v.y *= inv; v.z *= inv; v.w *= inv;
            o4[p] = v;
        }
    }
}

// ---------------- launch ----------------
extern "C" void kernel_launch(void* const* d_in, const int* in_sizes, int n_in,
                              void* d_out, int out_size) {
    const float* q   = (const float*)d_in[0];
    const float* k   = (const float*)d_in[1];
    const float* mem = (const float*)d_in[2];
    float* out = (float*)d_out;

    cudaFuncSetAttribute(gemm_k, cudaFuncAttributeMaxDynamicSharedMemorySize, 196608);

    splitmain_k<<<SPLIT_GRID, 256>>>(q, k, mem, out);
    gemm_k<<<GRID_GEMM, GTHREADS, 196608>>>(out, k, mem);
}

// round 15
// speedup vs baseline: 1.0362x; 1.0362x over previous
#include <cuda_runtime.h>
#include <cuda_bf16.h>
#include <cstdint>

// ---------------- problem constants ----------------
#define BSZ   256
#define DIM   128
#define QK    131072
#define NC    131073
#define OUT_ELEMS (BSZ * (long long)NC)      // 33,554,688
#define PROBS_OFF OUT_ELEMS
#define MEM_OFF   (OUT_ELEMS + 1)
#define T_INV 14.2857142857142857f
#define OUTPUT_SIZE 1000000.0f
#define GRID_GEMM 148
#define NTILES    2048                        // 1024 bn x 2 bm
#define GTHREADS  512

// split kernel block layout
#define MEMBLKS  8192      // mem: 4,194,304 float4 / 2 per thread / 256
#define QBLKS    16        // q: 8,192 float4 / 2 per thread / 256
#define SPLIT_GRID (MEMBLKS + QBLKS + 1)

// ---------------- device scratch ----------------
__device__ float g_rowsum[BSZ];
__device__ float g_invZ;
__device__ int   g_done = 0;    // monotonic ticket counter (modulo use, never reset)
__device__ __nv_bfloat16 g_mem_hi[QK * DIM];   // 32 MB
__device__ __nv_bfloat16 g_mem_lo[QK * DIM];   // 32 MB
__device__ __nv_bfloat16 g_q_hi[BSZ * DIM];
__device__ __nv_bfloat16 g_q_lo[BSZ * DIM];

// ---------------- helpers ----------------
__device__ __forceinline__ uint32_t smem_u32(const void* p) {
    uint32_t a;
    asm("{ .reg .u64 t; cvta.to.shared.u64 t, %1; cvt.u32.u64 %0, t; }" : "=r"(a) : "l"(p));
    return a;
}
__device__ __forceinline__ void ldm_x4(uint32_t* r, uint32_t addr) {
    asm volatile("ldmatrix.sync.aligned.m8n8.x4.shared.b16 {%0,%1,%2,%3}, [%4];"
                 : "=r"(r[0]), "=r"(r[1]), "=r"(r[2]), "=r"(r[3]) : "r"(addr));
}
__device__ __forceinline__ void mma_bf16(float* d, const uint32_t* a, uint32_t b0, uint32_t b1) {
    asm volatile(
        "mma.sync.aligned.m16n8k16.row.col.f32.bf16.bf16.f32 "
        "{%0,%1,%2,%3}, {%4,%5,%6,%7}, {%8,%9}, {%0,%1,%2,%3};"
        : "+f"(d[0]), "+f"(d[1]), "+f"(d[2]), "+f"(d[3])
        : "r"(a[0]), "r"(a[1]), "r"(a[2]), "r"(a[3]), "r"(b0), "r"(b1));
}
#define CP_ASYNC16(dst, src) \
    asm volatile("{ .reg .u64 g; cvta.to.global.u64 g, %1; cp.async.cg.shared.global [%0], [g], 16; }" \
                 :: "r"(dst), "l"(src) : "memory")
#define CP_COMMIT() asm volatile("cp.async.commit_group;" ::: "memory")
#define CP_WAIT1()  asm volatile("cp.async.wait_group 1;" ::: "memory")
#define CP_WAIT0()  asm volatile("cp.async.wait_group 0;" ::: "memory")

// ---- packed f32x2 ----
__device__ __forceinline__ unsigned long long dup2(float x) {
    unsigned long long r; unsigned int u = __float_as_uint(x);
    asm("mov.b64 %0, {%1, %1};" : "=l"(r) : "r"(u));
    return r;
}
__device__ __forceinline__ unsigned long long fma2(unsigned long long a,
                                                   unsigned long long b,
                                                   unsigned long long c) {
    unsigned long long d;
    asm("fma.rn.f32x2 %0, %1, %2, %3;" : "=l"(d) : "l"(a), "l"(b), "l"(c));
    return d;
}
__device__ __forceinline__ unsigned long long add2(unsigned long long a, unsigned long long b) {
    unsigned long long d;
    asm("add.rn.f32x2 %0, %1, %2;" : "=l"(d) : "l"(a), "l"(b));
    return d;
}
__device__ __forceinline__ unsigned long long mul2(unsigned long long a, unsigned long long b) {
    unsigned long long d;
    asm("mul.rn.f32x2 %0, %1, %2;" : "=l"(d) : "l"(a), "l"(b));
    return d;
}

// exp(s/T) for a pair, via packed exp2 on the FMA pipe.
__device__ __forceinline__ float2 exp_pair(float a, float b) {
    unsigned long long sp;
    asm("mov.b64 %0, {%1,%2};" : "=l"(sp) : "f"(a), "f"(b));
    const unsigned long long S  = dup2(20.60992908f);       // (1/0.07)*log2(e)
    const unsigned long long MG = dup2(12582912.0f);        // 1.5*2^23
    unsigned long long t  = fma2(sp, S, MG);
    unsigned long long nf = add2(t, dup2(-12582912.0f));    // n as float
    unsigned long long f  = fma2(sp, S, nf ^ 0x8000000080000000ULL);  // y - n
    unsigned long long r  = fma2(f, dup2(0.00133335581464f), dup2(0.00961812910763f));
    r = fma2(r, f, dup2(0.0555041086648f));
    r = fma2(r, f, dup2(0.240226506959f));
    r = fma2(r, f, dup2(0.69314718056f));
    r = fma2(r, f, dup2(1.0f));
    uint32_t t0, t1;
    asm("mov.b64 {%0,%1}, %2;" : "=r"(t0), "=r"(t1) : "l"(t));
    uint32_t sb0 = (t0 << 23) + 0x3F800000u;
    uint32_t sb1 = (t1 << 23) + 0x3F800000u;
    unsigned long long sc;
    asm("mov.b64 %0, {%1,%2};" : "=l"(sc) : "r"(sb0), "r"(sb1));
    unsigned long long res = mul2(r, sc);
    float x, y;
    asm("mov.b64 {%0,%1}, %2;" : "=f"(x), "=f"(y) : "l"(res));
    return make_float2(x, y);
}

// ---- ZERO-CVT truncating split: two floats -> hi bf16x2 + lo bf16x2 ----
// hi = top-16 bits (truncation), lo = trunc16(x - hi). No F2F-pipe ops:
// 2 PRMT + 2 LOP (alu) + 2 FSUB (fma) per 2 floats.
__device__ __forceinline__ void split2(float x, float y, uint32_t& hi, uint32_t& lo) {
    uint32_t bx = __float_as_uint(x), by = __float_as_uint(y);
    hi = __byte_perm(bx, by, 0x7632);                      // [x_hi16 | y_hi16]
    float rx = x - __uint_as_float(bx & 0xFFFF0000u);
    float ry = y - __uint_as_float(by & 0xFFFF0000u);
    lo = __byte_perm(__float_as_uint(rx), __float_as_uint(ry), 0x7632);
}
// 8 consecutive floats (2 float4) -> hi uint4 + lo uint4
__device__ __forceinline__ void split8(float4 v0, float4 v1, uint4& hi, uint4& lo) {
    split2(v0.x, v0.y, hi.x, lo.x);
    split2(v0.z, v0.w, hi.y, lo.y);
    split2(v1.x, v1.y, hi.z, lo.z);
    split2(v1.z, v1.w, hi.w, lo.w);
}

// ---------------- K0: loop-free split + zero + l_pos ----------------
__global__ void splitmain_k(const float* __restrict__ q, const float* __restrict__ k,
                            const float* __restrict__ mem, float* __restrict__ out) {
    int b = blockIdx.x;
    int t = threadIdx.x;
    if (b < MEMBLKS) {
        int tid = b * 256 + t;                 // < 2,097,152
        const float4* src = reinterpret_cast<const float4*>(mem) + tid * 2;
        float4 v0 = src[0];
        float4 v1 = src[1];
        uint4 hi, lo;
        split8(v0, v1, hi, lo);
        reinterpret_cast<uint4*>(g_mem_hi)[tid] = hi;
        reinterpret_cast<uint4*>(g_mem_lo)[tid] = lo;
    } else if (b < MEMBLKS + QBLKS) {
        int tid = (b - MEMBLKS) * 256 + t;     // < 4096
        const float4* src = reinterpret_cast<const float4*>(q) + tid * 2;
        float4 v0 = src[0];
        float4 v1 = src[1];
        uint4 hi, lo;
        split8(v0, v1, hi, lo);
        reinterpret_cast<uint4*>(g_q_hi)[tid] = hi;
        reinterpret_cast<uint4*>(g_q_lo)[tid] = lo;
    } else {
        // zero rowsums + l_pos column
        g_rowsum[t] = 0.f;
        __syncthreads();
        int vid = t & 63;
        const float* qb = q + t * DIM;
        float s = 0.f;
        #pragma unroll
        for (int c = 0; c < 4; c++) {
            int r = vid + c * 64;
            if (r == t) continue;
            const float* kr = k + r * DIM;
            float d = 0.f;
            #pragma unroll
            for (int j = 0; j < DIM; j++) d += kr[j] * qb[j];
            s += d;
        }
        s *= (1.0f / 3.0f);
        float e = __expf(s * T_INV);
        out[(long long)t * NC] = e;
        atomicAdd(&g_rowsum[t], e);
    }
}

// ---------------- K1: persistent GEMM + memup + last-CTA finalize --------
// SMEM 192KB: A hi/lo (64KB resident, 128 rows) + two B buffers (64KB each).
extern __shared__ char smem_g[];

__device__ __forceinline__ void issueB(int bn, int buf, uint32_t sbase, int t) {
    const uint4* hi = reinterpret_cast<const uint4*>(g_mem_hi) + (size_t)bn * 2048;
    const uint4* lo = reinterpret_cast<const uint4*>(g_mem_lo) + (size_t)bn * 2048;
    uint32_t base = sbase + 65536 + (uint32_t)buf * 65536;
    #pragma unroll
    for (int it = 0; it < 8; it++) {
        int fid = it * GTHREADS + t;
        int arr = fid >> 11;
        int within = fid & 2047;
        int row = within >> 4, ch = within & 15;
        const uint4* src = (arr ? lo : hi) + row * 16 + ch;
        uint32_t dst = base + (uint32_t)(arr * 32768 + row * 256 + ((ch ^ (row & 7)) << 4));
        CP_ASYNC16(dst, src);
    }
}
__device__ __forceinline__ void stageA(int bm, int t) {
    const uint4* hi = reinterpret_cast<const uint4*>(g_q_hi) + (size_t)bm * 2048;
    const uint4* lo = reinterpret_cast<const uint4*>(g_q_lo) + (size_t)bm * 2048;
    #pragma unroll
    for (int it = 0; it < 8; it++) {
        int fid = it * GTHREADS + t;
        int arr = fid >> 11;
        int within = fid & 2047;
        int row = within >> 4, ch = within & 15;
        uint4 v = (arr ? lo : hi)[row * 16 + ch];
        *reinterpret_cast<uint4*>(smem_g + arr * 32768 + row * 256 + ((ch ^ (row & 7)) << 4)) = v;
    }
}

__global__ __launch_bounds__(GTHREADS, 1)
void gemm_k(float* __restrict__ out, const float* __restrict__ kk,
            const float* __restrict__ memp) {
    __shared__ int isLast;
    uint32_t sbase = smem_u32(smem_g);
    int t = threadIdx.x;
    int w = t >> 5, lane = t & 31;
    int wm = w >> 2, wn = w & 3;          // 4x4 warps; warp tile 32 rows x 32 cols
    int a_r = (lane & 7) + ((lane >> 3) & 1) * 8;
    int a_c = (lane >> 4) & 1;
    int b_r = (lane & 7) + ((lane >> 4) & 1) * 8;
    int b_c = (lane >> 3) & 1;
    int grp = lane >> 2, tid4 = lane & 3;

    float rs[2][2] = {{0.f, 0.f}, {0.f, 0.f}};

    int tile0 = blockIdx.x;
    int curBm = tile0 >> 10;

    issueB(tile0 & 1023, 0, sbase, t);
    CP_COMMIT();
    stageA(curBm, t);

    const uint32_t AH = sbase, AL = sbase + 32768;

    int idx = 0;
    for (int tile = tile0; tile < NTILES; tile += GRID_GEMM, idx++) {
        int nxt = tile + GRID_GEMM;
        if (nxt < NTILES) {
            issueB(nxt & 1023, (idx + 1) & 1, sbase, t);
            CP_COMMIT();
            CP_WAIT1();
        } else {
            CP_WAIT0();
        }
        __syncthreads();

        int bm = tile >> 10;
        if (bm != curBm) {
            #pragma unroll
            for (int mt = 0; mt < 2; mt++) {
                int r0 = curBm * 128 + wm * 32 + mt * 16 + grp;
                atomicAdd(&g_rowsum[r0], rs[mt][0]);
                atomicAdd(&g_rowsum[r0 + 8], rs[mt][1]);
                rs[mt][0] = rs[mt][1] = 0.f;
            }
            curBm = bm;
            stageA(bm, t);
            __syncthreads();
        }

        uint32_t BH = sbase + 65536 + (uint32_t)(idx & 1) * 65536;
        uint32_t BL = BH + 32768;
        int bn = tile & 1023;

        float acc[2][4][4];
        #pragma unroll
        for (int mt = 0; mt < 2; mt++)
            #pragma unroll
            for (int nt = 0; nt < 4; nt++)
                #pragma unroll
                for (int r = 0; r < 4; r++) acc[mt][nt][r] = 0.f;

        #pragma unroll
        for (int ks = 0; ks < 8; ks++) {
            uint32_t ah[2][4], al[2][4];
            #pragma unroll
            for (int mt = 0; mt < 2; mt++) {
                int r = wm * 32 + mt * 16 + a_r;
                int ch = ks * 2 + a_c;
                uint32_t off = (uint32_t)(r * 256 + ((ch ^ (r & 7)) << 4));
                ldm_x4(ah[mt], AH + off);
                ldm_x4(al[mt], AL + off);
            }
            #pragma unroll
            for (int np = 0; np < 2; np++) {
                int n = wn * 32 + np * 16 + b_r;
                int ch = ks * 2 + b_c;
                uint32_t off = (uint32_t)(n * 256 + ((ch ^ (n & 7)) << 4));
                uint32_t bh[4], bl[4];
                ldm_x4(bh, BH + off);
                ldm_x4(bl, BL + off);
                #pragma unroll
                for (int sub = 0; sub < 2; sub++) {
                    int nt = np * 2 + sub;
                    #pragma unroll
                    for (int mt = 0; mt < 2; mt++) {
                        mma_bf16(acc[mt][nt], ah[mt], bh[2 * sub], bh[2 * sub + 1]);
                        mma_bf16(acc[mt][nt], ah[mt], bl[2 * sub], bl[2 * sub + 1]);
                        mma_bf16(acc[mt][nt], al[mt], bh[2 * sub], bh[2 * sub + 1]);
                    }
                }
            }
        }

        // ---- epilogue: poly exp (FMA pipe), store, rowsum ----
        #pragma unroll
        for (int mt = 0; mt < 2; mt++) {
            int r0l = wm * 32 + mt * 16 + grp;
            long long m0 = (long long)(bm * 128 + r0l);
            long long base0 = m0 * NC + 1 + (long long)bn * 128 + wn * 32;
            long long base1 = base0 + 8LL * NC;
            float s0 = 0.f, s1 = 0.f;
            #pragma unroll
            for (int nt = 0; nt < 4; nt++) {
                int cb = nt * 8 + tid4 * 2;
                float2 p0 = exp_pair(acc[mt][nt][0], acc[mt][nt][1]);
                float2 p1 = exp_pair(acc[mt][nt][2], acc[mt][nt][3]);
                out[base0 + cb]     = p0.x;
                out[base0 + cb + 1] = p0.y;
                out[base1 + cb]     = p1.x;
                out[base1 + cb + 1] = p1.y;
                s0 += p0.x + p0.y;
                s1 += p1.x + p1.y;
            }
            rs[mt][0] += s0; rs[mt][1] += s1;
        }
        __syncthreads();
    }

    #pragma unroll
    for (int mt = 0; mt < 2; mt++) {
        int r0 = curBm * 128 + wm * 32 + mt * 16 + grp;
        atomicAdd(&g_rowsum[r0], rs[mt][0]);
        atomicAdd(&g_rowsum[r0 + 8], rs[mt][1]);
    }

    // ---- memup tail (independent of Z) ----
    {
        const long long N = (long long)QK * DIM;
        long long stride = (long long)GRID_GEMM * GTHREADS;
        for (long long p = (long long)blockIdx.x * GTHREADS + t; p < N; p += stride) {
            int r = (int)(p >> 7), d = (int)(p & 127);
            float v;
            if (r < 64) {
                v = 0.25f * (kk[r * DIM + d] + kk[(r + 64) * DIM + d] +
                             kk[(r + 128) * DIM + d] + kk[(r + 192) * DIM + d]);
            } else {
                v = memp[p];
            }
            out[MEM_OFF + p] = v;
        }
    }

    // ---- last-CTA finalize: Z, invZ, probs ----
    __threadfence();
    __syncthreads();
    if (t == 0) isLast = ((atomicAdd(&g_done, 1) % GRID_GEMM) == GRID_GEMM - 1);
    __syncthreads();
    if (isLast) {
        float* s = reinterpret_cast<float*>(smem_g);   // reuse dyn smem
        if (t < 256) {
            volatile float* vr = g_rowsum;
            float rsv = vr[t];
            float e0v = out[(long long)t * NC];
            s[t] = rsv;
            s[256 + t] = e0v / rsv;
        }
        __syncthreads();
        for (int st = 128; st > 0; st >>= 1) {
            if (t < st) { s[t] += s[t + st]; s[256 + t] += s[256 + t + st]; }
            __syncthreads();
        }
        if (t == 0) {
            float Z = s[0] / ((float)BSZ * (float)NC) * OUTPUT_SIZE;
            g_invZ = 1.f / Z;
            out[PROBS_OFF] = s[256] * (1.0f / 256.0f);
        }
    }
}

// ---------------- K2: scale out by 1/Z ----------------
__global__ void scale_k(float* __restrict__ out) {
    float inv = g_invZ;
    long long i = (long long)blockIdx.x * blockDim.x + threadIdx.x;
    long long stride = (long long)gridDim.x * blockDim.x;
    float4* o4 = reinterpret_cast<float4*>(out);
    const long long n4 = OUT_ELEMS / 4;
    for (long long p = i; p < n4; p += stride) {
        float4 v = o4[p];
        v.x *= inv; v.y *= inv; v.z *= inv; v.w *= inv;
        o4[p] = v;
    }
}

// ---------------- launch ----------------
extern "C" void kernel_launch(void* const* d_in, const int* in_sizes, int n_in,
                              void* d_out, int out_size) {
    const float* q   = (const float*)d_in[0];
    const float* k   = (const float*)d_in[1];
    const float* mem = (const float*)d_in[2];
    float* out = (float*)d_out;

    cudaFuncSetAttribute(gemm_k, cudaFuncAttributeMaxDynamicSharedMemorySize, 196608);

    splitmain_k<<<SPLIT_GRID, 256>>>(q, k, mem, out);
    gemm_k<<<GRID_GEMM, GTHREADS, 196608>>>(out, k, mem);
    scale_k<<<4096, 256>>>(out);
}

// round 16
// speedup vs baseline: 1.1214x; 1.0822x over previous
#include <cuda_runtime.h>
#include <cuda_bf16.h>
#include <cstdint>

// ---------------- problem constants ----------------
#define BSZ   256
#define DIM   128
#define QK    131072
#define NC    131073
#define OUT_ELEMS (BSZ * (long long)NC)      // 33,554,688
#define PROBS_OFF OUT_ELEMS
#define MEM_OFF   (OUT_ELEMS + 1)
#define T_INV 14.2857142857142857f
#define OUTPUT_SIZE 1000000.0f
#define GRID_GEMM 148
#define NTILES    2048                        // 1024 bn x 2 bm
#define GTHREADS  512

// split kernel layout: 512 thr, 8 float4 per thread, fully unrolled (MLP=8)
#define SP_MEMBLKS 1024    // 4,194,304 float4 / (512*8)
#define SP_QBLKS   2       // 8,192 float4 / (512*8)
#define SPLIT_GRID (SP_MEMBLKS + SP_QBLKS + 1)

// ---------------- device scratch ----------------
__device__ float g_rowsum[BSZ];
__device__ float g_invZ;
__device__ __nv_bfloat16 g_mem_hi[QK * DIM];   // 32 MB
__device__ __nv_bfloat16 g_mem_lo[QK * DIM];   // 32 MB
__device__ __nv_bfloat16 g_q_hi[BSZ * DIM];
__device__ __nv_bfloat16 g_q_lo[BSZ * DIM];

// ---------------- helpers ----------------
__device__ __forceinline__ uint32_t smem_u32(const void* p) {
    uint32_t a;
    asm("{ .reg .u64 t; cvta.to.shared.u64 t, %1; cvt.u32.u64 %0, t; }" : "=r"(a) : "l"(p));
    return a;
}
__device__ __forceinline__ void ldm_x4(uint32_t* r, uint32_t addr) {
    asm volatile("ldmatrix.sync.aligned.m8n8.x4.shared.b16 {%0,%1,%2,%3}, [%4];"
                 : "=r"(r[0]), "=r"(r[1]), "=r"(r[2]), "=r"(r[3]) : "r"(addr));
}
__device__ __forceinline__ void mma_bf16(float* d, const uint32_t* a, uint32_t b0, uint32_t b1) {
    asm volatile(
        "mma.sync.aligned.m16n8k16.row.col.f32.bf16.bf16.f32 "
        "{%0,%1,%2,%3}, {%4,%5,%6,%7}, {%8,%9}, {%0,%1,%2,%3};"
        : "+f"(d[0]), "+f"(d[1]), "+f"(d[2]), "+f"(d[3])
        : "r"(a[0]), "r"(a[1]), "r"(a[2]), "r"(a[3]), "r"(b0), "r"(b1));
}
#define CP_ASYNC16(dst, src) \
    asm volatile("{ .reg .u64 g; cvta.to.global.u64 g, %1; cp.async.cg.shared.global [%0], [g], 16; }" \
                 :: "r"(dst), "l"(src) : "memory")
#define CP_COMMIT() asm volatile("cp.async.commit_group;" ::: "memory")
#define CP_WAIT1()  asm volatile("cp.async.wait_group 1;" ::: "memory")
#define CP_WAIT0()  asm volatile("cp.async.wait_group 0;" ::: "memory")

// ---- packed f32x2 ----
__device__ __forceinline__ unsigned long long dup2(float x) {
    unsigned long long r; unsigned int u = __float_as_uint(x);
    asm("mov.b64 %0, {%1, %1};" : "=l"(r) : "r"(u));
    return r;
}
__device__ __forceinline__ unsigned long long fma2(unsigned long long a,
                                                   unsigned long long b,
                                                   unsigned long long c) {
    unsigned long long d;
    asm("fma.rn.f32x2 %0, %1, %2, %3;" : "=l"(d) : "l"(a), "l"(b), "l"(c));
    return d;
}
__device__ __forceinline__ unsigned long long add2(unsigned long long a, unsigned long long b) {
    unsigned long long d;
    asm("add.rn.f32x2 %0, %1, %2;" : "=l"(d) : "l"(a), "l"(b));
    return d;
}
__device__ __forceinline__ unsigned long long mul2(unsigned long long a, unsigned long long b) {
    unsigned long long d;
    asm("mul.rn.f32x2 %0, %1, %2;" : "=l"(d) : "l"(a), "l"(b));
    return d;
}

// exp(s/T) for a pair, via packed exp2 on the FMA pipe.
__device__ __forceinline__ float2 exp_pair(float a, float b) {
    unsigned long long sp;
    asm("mov.b64 %0, {%1,%2};" : "=l"(sp) : "f"(a), "f"(b));
    const unsigned long long S  = dup2(20.60992908f);       // (1/0.07)*log2(e)
    const unsigned long long MG = dup2(12582912.0f);        // 1.5*2^23
    unsigned long long t  = fma2(sp, S, MG);
    unsigned long long nf = add2(t, dup2(-12582912.0f));    // n as float
    unsigned long long f  = fma2(sp, S, nf ^ 0x8000000080000000ULL);  // y - n
    unsigned long long r  = fma2(f, dup2(0.00133335581464f), dup2(0.00961812910763f));
    r = fma2(r, f, dup2(0.0555041086648f));
    r = fma2(r, f, dup2(0.240226506959f));
    r = fma2(r, f, dup2(0.69314718056f));
    r = fma2(r, f, dup2(1.0f));
    uint32_t t0, t1;
    asm("mov.b64 {%0,%1}, %2;" : "=r"(t0), "=r"(t1) : "l"(t));
    uint32_t sb0 = (t0 << 23) + 0x3F800000u;
    uint32_t sb1 = (t1 << 23) + 0x3F800000u;
    unsigned long long sc;
    asm("mov.b64 %0, {%1,%2};" : "=l"(sc) : "r"(sb0), "r"(sb1));
    unsigned long long res = mul2(r, sc);
    float x, y;
    asm("mov.b64 {%0,%1}, %2;" : "=f"(x), "=f"(y) : "l"(res));
    return make_float2(x, y);
}

// ---- ZERO-CVT truncating split: two floats -> hi bf16x2 + lo bf16x2 ----
__device__ __forceinline__ void split2(float x, float y, uint32_t& hi, uint32_t& lo) {
    uint32_t bx = __float_as_uint(x), by = __float_as_uint(y);
    hi = __byte_perm(bx, by, 0x7632);                      // [x_hi16 | y_hi16]
    float rx = x - __uint_as_float(bx & 0xFFFF0000u);
    float ry = y - __uint_as_float(by & 0xFFFF0000u);
    lo = __byte_perm(__float_as_uint(rx), __float_as_uint(ry), 0x7632);
}

// ---------------- K0: MLP-batched split + l_pos ----------------
__global__ __launch_bounds__(512, 1)
void splitmain_k(const float* __restrict__ q, const float* __restrict__ k,
                 const float* __restrict__ mem, float* __restrict__ out) {
    int b = blockIdx.x;
    int t = threadIdx.x;
    if (b < SP_MEMBLKS + SP_QBLKS) {
        const float4* src;
        uint2 *dh, *dl;
        int base;
        if (b < SP_MEMBLKS) {
            src = reinterpret_cast<const float4*>(mem);
            dh = reinterpret_cast<uint2*>(g_mem_hi);
            dl = reinterpret_cast<uint2*>(g_mem_lo);
            base = b * 4096;
        } else {
            src = reinterpret_cast<const float4*>(q);
            dh = reinterpret_cast<uint2*>(g_q_hi);
            dl = reinterpret_cast<uint2*>(g_q_lo);
            base = (b - SP_MEMBLKS) * 4096;
        }
        // 8 independent loads issued up-front (MLP=8, front-batched by ptxas)
        float4 v[8];
        #pragma unroll
        for (int i = 0; i < 8; i++) v[i] = src[base + i * 512 + t];
        #pragma unroll
        for (int i = 0; i < 8; i++) {
            uint2 hi, lo;
            split2(v[i].x, v[i].y, hi.x, lo.x);
            split2(v[i].z, v[i].w, hi.y, lo.y);
            dh[base + i * 512 + t] = hi;
            dl[base + i * 512 + t] = lo;
        }
    } else if (t < 256) {
        // l_pos column (one block; direct store, no atomics needed)
        int vid = t & 63;
        const float* qb = q + t * DIM;
        float s = 0.f;
        #pragma unroll
        for (int c = 0; c < 4; c++) {
            int r = vid + c * 64;
            if (r == t) continue;
            const float* kr = k + r * DIM;
            float d = 0.f;
            #pragma unroll
            for (int j = 0; j < DIM; j++) d += kr[j] * qb[j];
            s += d;
        }
        s *= (1.0f / 3.0f);
        float e = __expf(s * T_INV);
        out[(long long)t * NC] = e;
        g_rowsum[t] = e;
    }
}

// ---------------- K1: persistent GEMM + memup tail (R9 structure) --------
// SMEM 192KB: A hi/lo (64KB resident, 128 rows) + two B buffers (64KB each).
extern __shared__ char smem_g[];

__device__ __forceinline__ void issueB(int bn, int buf, uint32_t sbase, int t) {
    const uint4* hi = reinterpret_cast<const uint4*>(g_mem_hi) + (size_t)bn * 2048;
    const uint4* lo = reinterpret_cast<const uint4*>(g_mem_lo) + (size_t)bn * 2048;
    uint32_t base = sbase + 65536 + (uint32_t)buf * 65536;
    #pragma unroll
    for (int it = 0; it < 8; it++) {
        int fid = it * GTHREADS + t;
        int arr = fid >> 11;
        int within = fid & 2047;
        int row = within >> 4, ch = within & 15;
        const uint4* src = (arr ? lo : hi) + row * 16 + ch;
        uint32_t dst = base + (uint32_t)(arr * 32768 + row * 256 + ((ch ^ (row & 7)) << 4));
        CP_ASYNC16(dst, src);
    }
}
__device__ __forceinline__ void stageA(int bm, int t) {
    const uint4* hi = reinterpret_cast<const uint4*>(g_q_hi) + (size_t)bm * 2048;
    const uint4* lo = reinterpret_cast<const uint4*>(g_q_lo) + (size_t)bm * 2048;
    #pragma unroll
    for (int it = 0; it < 8; it++) {
        int fid = it * GTHREADS + t;
        int arr = fid >> 11;
        int within = fid & 2047;
        int row = within >> 4, ch = within & 15;
        uint4 v = (arr ? lo : hi)[row * 16 + ch];
        *reinterpret_cast<uint4*>(smem_g + arr * 32768 + row * 256 + ((ch ^ (row & 7)) << 4)) = v;
    }
}

__global__ __launch_bounds__(GTHREADS, 1)
void gemm_k(float* __restrict__ out, const float* __restrict__ kk,
            const float* __restrict__ memp) {
    uint32_t sbase = smem_u32(smem_g);
    int t = threadIdx.x;
    int w = t >> 5, lane = t & 31;
    int wm = w >> 2, wn = w & 3;          // 4x4 warps; warp tile 32 rows x 32 cols
    int a_r = (lane & 7) + ((lane >> 3) & 1) * 8;
    int a_c = (lane >> 4) & 1;
    int b_r = (lane & 7) + ((lane >> 4) & 1) * 8;
    int b_c = (lane >> 3) & 1;
    int grp = lane >> 2, tid4 = lane & 3;

    float rs[2][2] = {{0.f, 0.f}, {0.f, 0.f}};

    int tile0 = blockIdx.x;
    int curBm = tile0 >> 10;

    issueB(tile0 & 1023, 0, sbase, t);
    CP_COMMIT();
    stageA(curBm, t);

    const uint32_t AH = sbase, AL = sbase + 32768;

    int idx = 0;
    for (int tile = tile0; tile < NTILES; tile += GRID_GEMM, idx++) {
        int nxt = tile + GRID_GEMM;
        if (nxt < NTILES) {
            issueB(nxt & 1023, (idx + 1) & 1, sbase, t);
            CP_COMMIT();
            CP_WAIT1();
        } else {
            CP_WAIT0();
        }
        __syncthreads();

        int bm = tile >> 10;
        if (bm != curBm) {
            #pragma unroll
            for (int mt = 0; mt < 2; mt++) {
                int r0 = curBm * 128 + wm * 32 + mt * 16 + grp;
                atomicAdd(&g_rowsum[r0], rs[mt][0]);
                atomicAdd(&g_rowsum[r0 + 8], rs[mt][1]);
                rs[mt][0] = rs[mt][1] = 0.f;
            }
            curBm = bm;
            stageA(bm, t);
            __syncthreads();
        }

        uint32_t BH = sbase + 65536 + (uint32_t)(idx & 1) * 65536;
        uint32_t BL = BH + 32768;
        int bn = tile & 1023;

        float acc[2][4][4];
        #pragma unroll
        for (int mt = 0; mt < 2; mt++)
            #pragma unroll
            for (int nt = 0; nt < 4; nt++)
                #pragma unroll
                for (int r = 0; r < 4; r++) acc[mt][nt][r] = 0.f;

        #pragma unroll
        for (int ks = 0; ks < 8; ks++) {
            uint32_t ah[2][4], al[2][4];
            #pragma unroll
            for (int mt = 0; mt < 2; mt++) {
                int r = wm * 32 + mt * 16 + a_r;
                int ch = ks * 2 + a_c;
                uint32_t off = (uint32_t)(r * 256 + ((ch ^ (r & 7)) << 4));
                ldm_x4(ah[mt], AH + off);
                ldm_x4(al[mt], AL + off);
            }
            #pragma unroll
            for (int np = 0; np < 2; np++) {
                int n = wn * 32 + np * 16 + b_r;
                int ch = ks * 2 + b_c;
                uint32_t off = (uint32_t)(n * 256 + ((ch ^ (n & 7)) << 4));
                uint32_t bh[4], bl[4];
                ldm_x4(bh, BH + off);
                ldm_x4(bl, BL + off);
                #pragma unroll
                for (int sub = 0; sub < 2; sub++) {
                    int nt = np * 2 + sub;
                    #pragma unroll
                    for (int mt = 0; mt < 2; mt++) {
                        mma_bf16(acc[mt][nt], ah[mt], bh[2 * sub], bh[2 * sub + 1]);
                        mma_bf16(acc[mt][nt], ah[mt], bl[2 * sub], bl[2 * sub + 1]);
                        mma_bf16(acc[mt][nt], al[mt], bh[2 * sub], bh[2 * sub + 1]);
                    }
                }
            }
        }

        // ---- epilogue: poly exp (FMA pipe), store, rowsum ----
        #pragma unroll
        for (int mt = 0; mt < 2; mt++) {
            int r0l = wm * 32 + mt * 16 + grp;
            long long m0 = (long long)(bm * 128 + r0l);
            long long base0 = m0 * NC + 1 + (long long)bn * 128 + wn * 32;
            long long base1 = base0 + 8LL * NC;
            float s0 = 0.f, s1 = 0.f;
            #pragma unroll
            for (int nt = 0; nt < 4; nt++) {
                int cb = nt * 8 + tid4 * 2;
                float2 p0 = exp_pair(acc[mt][nt][0], acc[mt][nt][1]);
                float2 p1 = exp_pair(acc[mt][nt][2], acc[mt][nt][3]);
                out[base0 + cb]     = p0.x;
                out[base0 + cb + 1] = p0.y;
                out[base1 + cb]     = p1.x;
                out[base1 + cb + 1] = p1.y;
                s0 += p0.x + p0.y;
                s1 += p1.x + p1.y;
            }
            rs[mt][0] += s0; rs[mt][1] += s1;
        }
        __syncthreads();
    }

    #pragma unroll
    for (int mt = 0; mt < 2; mt++) {
        int r0 = curBm * 128 + wm * 32 + mt * 16 + grp;
        atomicAdd(&g_rowsum[r0], rs[mt][0]);
        atomicAdd(&g_rowsum[r0 + 8], rs[mt][1]);
    }

    // ---- memup tail (independent of Z) ----
    {
        const long long N = (long long)QK * DIM;
        long long stride = (long long)GRID_GEMM * GTHREADS;
        for (long long p = (long long)blockIdx.x * GTHREADS + t; p < N; p += stride) {
            int r = (int)(p >> 7), d = (int)(p & 127);
            float v;
            if (r < 64) {
                v = 0.25f * (kk[r * DIM + d] + kk[(r + 64) * DIM + d] +
                             kk[(r + 128) * DIM + d] + kk[(r + 192) * DIM + d]);
            } else {
                v = memp[p];
            }
            out[MEM_OFF + p] = v;
        }
    }
}

// ---------------- K2: finalize Z, invZ, probs ----------------
__global__ void finalize_k(float* __restrict__ out) {
    __shared__ float sZ[256], sP[256];
    int t = threadIdx.x;
    float rsv = g_rowsum[t];
    float e0 = out[(long long)t * NC];
    sZ[t] = rsv;
    sP[t] = e0 / rsv;
    __syncthreads();
    for (int s = 128; s > 0; s >>= 1) {
        if (t < s) { sZ[t] += sZ[t + s]; sP[t] += sP[t + s]; }
        __syncthreads();
    }
    if (t == 0) {
        float Z = sZ[0] / ((float)BSZ * (float)NC) * OUTPUT_SIZE;
        g_invZ = 1.f / Z;
        out[PROBS_OFF] = sP[0] * (1.0f / 256.0f);
    }
}

// ---------------- K3: scale out by 1/Z ----------------
__global__ void scale_k(float* __restrict__ out) {
    float inv = g_invZ;
    long long i = (long long)blockIdx.x * blockDim.x + threadIdx.x;
    long long stride = (long long)gridDim.x * blockDim.x;
    float4* o4 = reinterpret_cast<float4*>(out);
    const long long n4 = OUT_ELEMS / 4;
    for (long long p = i; p < n4; p += stride) {
        float4 v = o4[p];
        v.x *= inv; v.y *= inv; v.z *= inv; v.w *= inv;
        o4[p] = v;
    }
}

// ---------------- launch ----------------
extern "C" void kernel_launch(void* const* d_in, const int* in_sizes, int n_in,
                              void* d_out, int out_size) {
    const float* q   = (const float*)d_in[0];
    const float* k   = (const float*)d_in[1];
    const float* mem = (const float*)d_in[2];
    float* out = (float*)d_out;

    cudaFuncSetAttribute(gemm_k, cudaFuncAttributeMaxDynamicSharedMemorySize, 196608);

    splitmain_k<<<SPLIT_GRID, 512>>>(q, k, mem, out);
    gemm_k<<<GRID_GEMM, GTHREADS, 196608>>>(out, k, mem);
    finalize_k<<<1, 256>>>(out);
    scale_k<<<4096, 256>>>(out);
}